// round 2
// baseline (speedup 1.0000x reference)
#include <cuda_runtime.h>
#include <cuda_bf16.h>

// Problem constants
#define CS   1024          // c_s = hidden
#define HH   16            // heads
#define DD   64            // head dim
#define CZ   128           // c_z
#define NEG_INF 1000000.0f

// -------- scratch (static device globals; no allocation allowed) --------
__device__ float g_q[CS * CS];        // [i, h*64+d]
__device__ float g_k[CS * CS];        // [j, h*64+d]
__device__ float g_v[CS * CS];        // [j, h*64+d]
__device__ float g_g[CS * CS];        // sigmoid gate [i, c]
__device__ float g_o[CS * CS];        // attention out [i, h*64+d]
__device__ float g_z[HH * CS * CS];   // pair bias [h, i, j]  (64 MB)

// ============================================================
// GEMM body (NT): C[M,N] = A[M,K] @ W[N,K]^T (+bias)(sigmoid)(A*=gate)
// M = N = K = 1024. Tile 64x64x16, 256 threads, 4x4 per thread.
// ============================================================
template <bool BIAS, bool SIG, bool GATE>
__device__ __forceinline__ void gemm_body(
    const float* __restrict__ A, const float* __restrict__ W,
    const float* __restrict__ bias, const float* __restrict__ gate,
    float* __restrict__ C)
{
    __shared__ float As[16][64];   // [k][m]
    __shared__ float Ws[16][64];   // [k][n]

    const int tid = threadIdx.x;
    const int tm  = tid >> 4;          // 0..15 (row group)
    const int tn  = tid & 15;          // 0..15 (col group)
    const int bm  = blockIdx.y * 64;
    const int bn  = blockIdx.x * 64;
    const int lr  = tid >> 2;          // 0..63 load row
    const int lc  = (tid & 3) << 2;    // 0,4,8,12 load k-offset

    float acc[4][4];
#pragma unroll
    for (int r = 0; r < 4; r++)
#pragma unroll
        for (int c = 0; c < 4; c++) acc[r][c] = 0.f;

    const float* Ap = A + (bm + lr) * CS + lc;
    const float* Wp = W + (bn + lr) * CS + lc;
    const float* Gp = GATE ? (gate + (bm + lr) * CS + lc) : nullptr;

    for (int k0 = 0; k0 < CS; k0 += 16) {
        float4 a4 = *(const float4*)(Ap + k0);
        if (GATE) {
            float4 g4 = *(const float4*)(Gp + k0);
            a4.x *= g4.x; a4.y *= g4.y; a4.z *= g4.z; a4.w *= g4.w;
        }
        float4 w4 = *(const float4*)(Wp + k0);
        __syncthreads();
        As[lc + 0][lr] = a4.x; As[lc + 1][lr] = a4.y;
        As[lc + 2][lr] = a4.z; As[lc + 3][lr] = a4.w;
        Ws[lc + 0][lr] = w4.x; Ws[lc + 1][lr] = w4.y;
        Ws[lc + 2][lr] = w4.z; Ws[lc + 3][lr] = w4.w;
        __syncthreads();
#pragma unroll
        for (int k = 0; k < 16; k++) {
            float av[4], wv[4];
            *(float4*)av = *(const float4*)&As[k][tm << 2];
            *(float4*)wv = *(const float4*)&Ws[k][tn << 2];
#pragma unroll
            for (int r = 0; r < 4; r++)
#pragma unroll
                for (int c = 0; c < 4; c++) acc[r][c] += av[r] * wv[c];
        }
    }

    float bv[4] = {0.f, 0.f, 0.f, 0.f};
    if (BIAS) {
#pragma unroll
        for (int c = 0; c < 4; c++) bv[c] = bias[bn + (tn << 2) + c];
    }
#pragma unroll
    for (int r = 0; r < 4; r++) {
        float out[4];
#pragma unroll
        for (int c = 0; c < 4; c++) {
            float vle = acc[r][c];
            if (BIAS) vle += bv[c];
            if (SIG)  vle = 1.f / (1.f + __expf(-vle));
            out[c] = vle;
        }
        *(float4*)&C[(bm + (tm << 2) + r) * CS + bn + (tn << 2)] = *(float4*)out;
    }
}

// Thin wrappers: scratch buffers referenced directly (no symbol lookup on host).
__global__ void __launch_bounds__(256) gemm_q(const float* __restrict__ s,
                                              const float* __restrict__ Wq,
                                              const float* __restrict__ bq) {
    gemm_body<true, false, false>(s, Wq, bq, nullptr, g_q);
}
__global__ void __launch_bounds__(256) gemm_k(const float* __restrict__ kin,
                                              const float* __restrict__ Wk) {
    gemm_body<false, false, false>(kin, Wk, nullptr, nullptr, g_k);
}
__global__ void __launch_bounds__(256) gemm_v(const float* __restrict__ kin,
                                              const float* __restrict__ Wv) {
    gemm_body<false, false, false>(kin, Wv, nullptr, nullptr, g_v);
}
__global__ void __launch_bounds__(256) gemm_g(const float* __restrict__ s,
                                              const float* __restrict__ Wg) {
    gemm_body<false, true, false>(s, Wg, nullptr, nullptr, g_g);
}
__global__ void __launch_bounds__(256) gemm_out(const float* __restrict__ Wo,
                                                float* __restrict__ out) {
    gemm_body<false, false, true>(g_o, Wo, nullptr, g_g, out);
}

// ============================================================
// z kernel: z[h, m] = sum_c bias[m, c] * Wz[c, h] + (1-mask[j])*(-INF)
//   m = i*1024 + j, bias is [1M, 128], Wz is [128, 16].
// Block = 256 consecutive m rows; thread = one m row, all 16 h in regs.
// Streams the 512 MB bias tensor exactly once.
// ============================================================
__global__ void __launch_bounds__(256) z_kernel(
    const float* __restrict__ bias, const float* __restrict__ Wz,
    const float* __restrict__ mask)
{
    __shared__ float wzs[CZ][HH];      // 8 KB
    __shared__ float bs[256][33];      // 33.8 KB, padded stride -> conflict-free

    const int tid = threadIdx.x;
    // load Wz (128*16 floats = 512 float4)
    for (int idx = tid; idx < (CZ * HH) / 4; idx += 256)
        ((float4*)wzs)[idx] = ((const float4*)Wz)[idx];

    const int m0 = blockIdx.x * 256;

    float acc[HH];
#pragma unroll
    for (int h = 0; h < HH; h++) acc[h] = 0.f;

    for (int c0 = 0; c0 < CZ; c0 += 32) {
        __syncthreads();
        // stage bias[m0..m0+255][c0..c0+31] : 2048 float4, 8 per thread, coalesced
#pragma unroll
        for (int it = 0; it < 8; it++) {
            int slot = tid + it * 256;          // 0..2047
            int mm   = slot >> 3;               // 0..255
            int c4   = (slot & 7) << 2;         // 0..28
            float4 b4 = *(const float4*)&bias[(m0 + mm) * CZ + c0 + c4];
            bs[mm][c4 + 0] = b4.x; bs[mm][c4 + 1] = b4.y;
            bs[mm][c4 + 2] = b4.z; bs[mm][c4 + 3] = b4.w;
        }
        __syncthreads();
#pragma unroll
        for (int cc = 0; cc < 32; cc++) {
            float b = bs[tid][cc];
            const float4* wrow = (const float4*)&wzs[c0 + cc][0];   // broadcast
            float4 w0 = wrow[0], w1 = wrow[1], w2 = wrow[2], w3 = wrow[3];
            acc[0]  += b * w0.x; acc[1]  += b * w0.y; acc[2]  += b * w0.z; acc[3]  += b * w0.w;
            acc[4]  += b * w1.x; acc[5]  += b * w1.y; acc[6]  += b * w1.z; acc[7]  += b * w1.w;
            acc[8]  += b * w2.x; acc[9]  += b * w2.y; acc[10] += b * w2.z; acc[11] += b * w2.w;
            acc[12] += b * w3.x; acc[13] += b * w3.y; acc[14] += b * w3.z; acc[15] += b * w3.w;
        }
    }

    const int m = m0 + tid;
    const float madd = (1.f - mask[m & (CS - 1)]) * (-NEG_INF);
#pragma unroll
    for (int h = 0; h < HH; h++)
        g_z[h * (CS * CS) + m] = acc[h] + madd;
}

// ============================================================
// Flash attention: block = (head h, 64-row i tile). TJ = 32.
// o[i, h*64+d] = softmax(q k^T / 8 + z) @ v   (online softmax)
// k/v per head = 512 KB; total k+v 8 MB lives in L2 across blocks.
// ============================================================
__global__ void __launch_bounds__(256) attn_kernel()
{
    __shared__ float Qs[64][64];     // [d][i]
    __shared__ float Ks[64][32];     // [d][j]
    __shared__ float Vs[32][64];     // [j][d]
    __shared__ float Ss[64][33];     // logits / probs, padded
    __shared__ float m_s[64], l_s[64], scale_s[64];

    const int tid = threadIdx.x;
    const int h   = blockIdx.y;
    const int i0  = blockIdx.x * 64;
    const int tm  = tid >> 4;        // 0..15
    const int tn  = tid & 15;        // 0..15

    // load + transpose Q tile
#pragma unroll
    for (int it = 0; it < 4; it++) {
        int slot = tid + it * 256;          // 0..1023
        int i    = slot >> 4;               // 0..63
        int d4   = (slot & 15) << 2;        // 0..60
        float4 q4 = *(const float4*)&g_q[(i0 + i) * CS + h * DD + d4];
        Qs[d4 + 0][i] = q4.x; Qs[d4 + 1][i] = q4.y;
        Qs[d4 + 2][i] = q4.z; Qs[d4 + 3][i] = q4.w;
    }
    if (tid < 64) { m_s[tid] = -1e30f; l_s[tid] = 0.f; }

    float oacc[4][4];
#pragma unroll
    for (int r = 0; r < 4; r++)
#pragma unroll
        for (int c = 0; c < 4; c++) oacc[r][c] = 0.f;

    __syncthreads();

    for (int j0 = 0; j0 < CS; j0 += 32) {
        // load K (transposed) and V tiles
#pragma unroll
        for (int it = 0; it < 2; it++) {
            int slot = tid + it * 256;      // 0..511
            int j    = slot >> 4;           // 0..31
            int d4   = (slot & 15) << 2;
            float4 k4 = *(const float4*)&g_k[(j0 + j) * CS + h * DD + d4];
            Ks[d4 + 0][j] = k4.x; Ks[d4 + 1][j] = k4.y;
            Ks[d4 + 2][j] = k4.z; Ks[d4 + 3][j] = k4.w;
            float4 v4 = *(const float4*)&g_v[(j0 + j) * CS + h * DD + d4];
            *(float4*)&Vs[j][d4] = v4;
        }
        __syncthreads();

        // S = Q K^T : thread owns rows tm*4..+3, cols tn*2..+1
        float sacc[4][2];
#pragma unroll
        for (int r = 0; r < 4; r++) { sacc[r][0] = 0.f; sacc[r][1] = 0.f; }
#pragma unroll
        for (int d = 0; d < DD; d++) {
            float qa[4];
            *(float4*)qa = *(const float4*)&Qs[d][tm << 2];
            float2 kb = *(const float2*)&Ks[d][tn << 1];
#pragma unroll
            for (int r = 0; r < 4; r++) {
                sacc[r][0] += qa[r] * kb.x;
                sacc[r][1] += qa[r] * kb.y;
            }
        }
        // write logits: qk/8 + z
#pragma unroll
        for (int r = 0; r < 4; r++) {
            int gi = i0 + (tm << 2) + r;
            float2 z2 = *(const float2*)&g_z[h * (CS * CS) + gi * CS + j0 + (tn << 1)];
            Ss[(tm << 2) + r][(tn << 1) + 0] = sacc[r][0] * 0.125f + z2.x;
            Ss[(tm << 2) + r][(tn << 1) + 1] = sacc[r][1] * 0.125f + z2.y;
        }
        __syncthreads();

        // online softmax row statistics: 4 threads per row, 8 j each
        {
            const int row = tid >> 2, seg = tid & 3;
            float mx = -1e30f;
#pragma unroll
            for (int jj = 0; jj < 8; jj++)
                mx = fmaxf(mx, Ss[row][(seg << 3) + jj]);
            mx = fmaxf(mx, __shfl_xor_sync(0xffffffffu, mx, 1));
            mx = fmaxf(mx, __shfl_xor_sync(0xffffffffu, mx, 2));
            const float m_old = m_s[row];
            const float m_new = fmaxf(m_old, mx);
            float sum = 0.f;
#pragma unroll
            for (int jj = 0; jj < 8; jj++) {
                float p = __expf(Ss[row][(seg << 3) + jj] - m_new);
                Ss[row][(seg << 3) + jj] = p;
                sum += p;
            }
            sum += __shfl_xor_sync(0xffffffffu, sum, 1);
            sum += __shfl_xor_sync(0xffffffffu, sum, 2);
            if (seg == 0) {
                float sc = __expf(m_old - m_new);
                l_s[row] = l_s[row] * sc + sum;
                m_s[row] = m_new;
                scale_s[row] = sc;
            }
        }
        __syncthreads();

        // rescale o, accumulate P @ V (thread owns rows tm*4..+3, d cols tn*4..+3)
        float scr[4];
#pragma unroll
        for (int r = 0; r < 4; r++) scr[r] = scale_s[(tm << 2) + r];
#pragma unroll
        for (int r = 0; r < 4; r++)
#pragma unroll
            for (int c = 0; c < 4; c++) oacc[r][c] *= scr[r];

#pragma unroll
        for (int j = 0; j < 32; j++) {
            float vv[4];
            *(float4*)vv = *(const float4*)&Vs[j][tn << 2];
            float p0 = Ss[(tm << 2) + 0][j];
            float p1 = Ss[(tm << 2) + 1][j];
            float p2 = Ss[(tm << 2) + 2][j];
            float p3 = Ss[(tm << 2) + 3][j];
#pragma unroll
            for (int c = 0; c < 4; c++) {
                oacc[0][c] += p0 * vv[c];
                oacc[1][c] += p1 * vv[c];
                oacc[2][c] += p2 * vv[c];
                oacc[3][c] += p3 * vv[c];
            }
        }
        __syncthreads();
    }

    // finalize: divide by l, write o[i, h*64+d]
#pragma unroll
    for (int r = 0; r < 4; r++) {
        float inv = 1.f / l_s[(tm << 2) + r];
        float out[4];
#pragma unroll
        for (int c = 0; c < 4; c++) out[c] = oacc[r][c] * inv;
        *(float4*)&g_o[(i0 + (tm << 2) + r) * CS + h * DD + (tn << 2)] = *(float4*)out;
    }
}

// ============================================================
// launch — kernel launches ONLY (trivially graph-capturable)
// ============================================================
extern "C" void kernel_launch(void* const* d_in, const int* in_sizes, int n_in,
                              void* d_out, int out_size)
{
    const float* s    = (const float*)d_in[0];
    const float* k_in = (const float*)d_in[1];
    const float* mask = (const float*)d_in[2];
    const float* bias = (const float*)d_in[3];
    const float* Wq   = (const float*)d_in[4];
    const float* bq   = (const float*)d_in[5];
    const float* Wk   = (const float*)d_in[6];
    const float* Wv   = (const float*)d_in[7];
    const float* Wg   = (const float*)d_in[8];
    const float* Wo   = (const float*)d_in[9];
    const float* Wz   = (const float*)d_in[10];
    // d_in[11] = multiplicity (==1 for b=1) -> identity, ignored
    float* out = (float*)d_out;

    dim3 gg(CS / 64, CS / 64);   // 16 x 16

    // projections
    gemm_q<<<gg, 256>>>(s, Wq, bq);
    gemm_k<<<gg, 256>>>(k_in, Wk);
    gemm_v<<<gg, 256>>>(k_in, Wv);
    gemm_g<<<gg, 256>>>(s, Wg);

    // pair bias -> z[h,i,j] (+mask)
    z_kernel<<<(CS * CS) / 256, 256>>>(bias, Wz, mask);

    // attention
    attn_kernel<<<dim3(CS / 64, HH), 256>>>();

    // out = (g .* o) @ Wo^T
    gemm_out<<<gg, 256>>>(Wo, out);
}

// round 3
// speedup vs baseline: 1.4942x; 1.4942x over previous
#include <cuda_runtime.h>
#include <cuda_bf16.h>
#include <cstdint>

// Problem constants
#define CS   1024          // c_s = hidden
#define HH   16            // heads
#define DD   64            // head dim
#define CZ   128           // c_z
#define NEG_INF 1000000.0f

// -------- scratch (static device globals; no allocation allowed) --------
__device__ float g_q[CS * CS];        // [i, h*64+d]
__device__ float g_k[CS * CS];        // [j, h*64+d]
__device__ float g_v[CS * CS];        // [j, h*64+d]
__device__ float g_g[CS * CS];        // sigmoid gate [i, c]
__device__ float g_o[CS * CS];        // attention out [i, h*64+d]
__device__ float g_z[HH * CS * CS];   // pair bias [h, i, j]  (64 MB)

// ---------------- tf32 helpers ----------------
__device__ __forceinline__ uint32_t f2tf(float x) {
    uint32_t r;
    asm("cvt.rna.tf32.f32 %0, %1;" : "=r"(r) : "f"(x));
    return r;
}

// D += A * B  (m16n8k8, tf32 in, f32 out)
__device__ __forceinline__ void mma_tf32(float c[4], const uint32_t a[4], const uint32_t b[2]) {
    asm volatile(
        "mma.sync.aligned.m16n8k8.row.col.f32.tf32.tf32.f32 "
        "{%0,%1,%2,%3}, {%4,%5,%6,%7}, {%8,%9}, {%0,%1,%2,%3};"
        : "+f"(c[0]), "+f"(c[1]), "+f"(c[2]), "+f"(c[3])
        : "r"(a[0]), "r"(a[1]), "r"(a[2]), "r"(a[3]),
          "r"(b[0]), "r"(b[1]));
}

// ============================================================
// tf32 tensor-core GEMM (NT): C[M,N] = A[M,K] @ W[N,K]^T
//   (+bias)(sigmoid)(A *= gate elementwise)
// Block tile 128x64, BK=32. 256 threads = 8 warps.
// Warp grid 4(m) x 2(n): warp tile 32x32 = 2 m-atoms x 4 n-atoms.
// Smem strides = 36 words (== 4 mod 32) -> conflict-free fragment LDS.
// ============================================================
template <bool BIAS, bool SIG, bool GATE>
__device__ __forceinline__ void mmgemm_body(
    const float* __restrict__ A, const float* __restrict__ W,
    const float* __restrict__ bias, const float* __restrict__ gate,
    float* __restrict__ C)
{
    __shared__ uint32_t As[128][36];   // tf32 bits, [m][k]
    __shared__ uint32_t Ws[64][36];    // tf32 bits, [n][k]

    const int tid  = threadIdx.x;
    const int w    = tid >> 5;
    const int lane = tid & 31;
    const int g    = lane >> 2;        // 0..7
    const int tq   = lane & 3;         // 0..3
    const int wm   = (w & 3) * 32;     // warp m offset in tile
    const int wn   = (w >> 2) * 32;    // warp n offset in tile
    const int bm   = blockIdx.y * 128;
    const int bn   = blockIdx.x * 64;

    float acc[2][4][4];
#pragma unroll
    for (int ma = 0; ma < 2; ma++)
#pragma unroll
        for (int na = 0; na < 4; na++)
#pragma unroll
            for (int r = 0; r < 4; r++) acc[ma][na][r] = 0.f;

    const int lrow = tid >> 3;            // 0..31
    const int lc4  = (tid & 7) << 2;      // 0,4,...,28

    for (int k0 = 0; k0 < CS; k0 += 32) {
        __syncthreads();
        // stage A tile (128 x 32), tf32-convert, gate if needed
#pragma unroll
        for (int it = 0; it < 4; it++) {
            int row = lrow + it * 32;
            float4 a4 = *(const float4*)&A[(bm + row) * CS + k0 + lc4];
            if (GATE) {
                float4 g4 = *(const float4*)&gate[(bm + row) * CS + k0 + lc4];
                a4.x *= g4.x; a4.y *= g4.y; a4.z *= g4.z; a4.w *= g4.w;
            }
            As[row][lc4 + 0] = f2tf(a4.x); As[row][lc4 + 1] = f2tf(a4.y);
            As[row][lc4 + 2] = f2tf(a4.z); As[row][lc4 + 3] = f2tf(a4.w);
        }
        // stage W tile (64 x 32)
#pragma unroll
        for (int it = 0; it < 2; it++) {
            int row = lrow + it * 32;
            float4 w4 = *(const float4*)&W[(bn + row) * CS + k0 + lc4];
            Ws[row][lc4 + 0] = f2tf(w4.x); Ws[row][lc4 + 1] = f2tf(w4.y);
            Ws[row][lc4 + 2] = f2tf(w4.z); Ws[row][lc4 + 3] = f2tf(w4.w);
        }
        __syncthreads();

#pragma unroll
        for (int kk = 0; kk < 4; kk++) {
            const int kb = kk * 8;
            uint32_t af[2][4];
#pragma unroll
            for (int ma = 0; ma < 2; ma++) {
                const int mb = wm + ma * 16;
                af[ma][0] = As[mb + g][kb + tq];
                af[ma][1] = As[mb + g + 8][kb + tq];
                af[ma][2] = As[mb + g][kb + tq + 4];
                af[ma][3] = As[mb + g + 8][kb + tq + 4];
            }
            uint32_t bf[4][2];
#pragma unroll
            for (int na = 0; na < 4; na++) {
                const int nb = wn + na * 8 + g;
                bf[na][0] = Ws[nb][kb + tq];
                bf[na][1] = Ws[nb][kb + tq + 4];
            }
#pragma unroll
            for (int ma = 0; ma < 2; ma++)
#pragma unroll
                for (int na = 0; na < 4; na++)
                    mma_tf32(acc[ma][na], af[ma], bf[na]);
        }
    }

    // epilogue
#pragma unroll
    for (int ma = 0; ma < 2; ma++) {
        const int m0 = bm + wm + ma * 16 + g;
#pragma unroll
        for (int na = 0; na < 4; na++) {
            const int n0 = bn + wn + na * 8 + tq * 2;
            float v0 = acc[ma][na][0], v1 = acc[ma][na][1];
            float v2 = acc[ma][na][2], v3 = acc[ma][na][3];
            if (BIAS) {
                float b0 = bias[n0], b1 = bias[n0 + 1];
                v0 += b0; v1 += b1; v2 += b0; v3 += b1;
            }
            if (SIG) {
                v0 = 1.f / (1.f + __expf(-v0));
                v1 = 1.f / (1.f + __expf(-v1));
                v2 = 1.f / (1.f + __expf(-v2));
                v3 = 1.f / (1.f + __expf(-v3));
            }
            *(float2*)&C[m0 * CS + n0]       = make_float2(v0, v1);
            *(float2*)&C[(m0 + 8) * CS + n0] = make_float2(v2, v3);
        }
    }
}

__global__ void __launch_bounds__(256) gemm_q(const float* __restrict__ s,
                                              const float* __restrict__ Wq,
                                              const float* __restrict__ bq) {
    mmgemm_body<true, false, false>(s, Wq, bq, nullptr, g_q);
}
__global__ void __launch_bounds__(256) gemm_k(const float* __restrict__ kin,
                                              const float* __restrict__ Wk) {
    mmgemm_body<false, false, false>(kin, Wk, nullptr, nullptr, g_k);
}
__global__ void __launch_bounds__(256) gemm_v(const float* __restrict__ kin,
                                              const float* __restrict__ Wv) {
    mmgemm_body<false, false, false>(kin, Wv, nullptr, nullptr, g_v);
}
__global__ void __launch_bounds__(256) gemm_g(const float* __restrict__ s,
                                              const float* __restrict__ Wg) {
    mmgemm_body<false, true, false>(s, Wg, nullptr, nullptr, g_g);
}
__global__ void __launch_bounds__(256) gemm_out(const float* __restrict__ Wo,
                                                float* __restrict__ out) {
    mmgemm_body<false, false, true>(g_o, Wo, nullptr, g_g, out);
}

// ============================================================
// z kernel: z[h, m] = sum_c bias[m, c] * Wz[c, h] + (1-mask[j])*(-INF)
// Streams the 512 MB bias tensor exactly once. (HBM-floor bound.)
// ============================================================
__global__ void __launch_bounds__(256) z_kernel(
    const float* __restrict__ bias, const float* __restrict__ Wz,
    const float* __restrict__ mask)
{
    __shared__ float wzs[CZ][HH];
    __shared__ float bs[256][33];

    const int tid = threadIdx.x;
    for (int idx = tid; idx < (CZ * HH) / 4; idx += 256)
        ((float4*)wzs)[idx] = ((const float4*)Wz)[idx];

    const int m0 = blockIdx.x * 256;

    float acc[HH];
#pragma unroll
    for (int h = 0; h < HH; h++) acc[h] = 0.f;

    for (int c0 = 0; c0 < CZ; c0 += 32) {
        __syncthreads();
#pragma unroll
        for (int it = 0; it < 8; it++) {
            int slot = tid + it * 256;
            int mm   = slot >> 3;
            int c4   = (slot & 7) << 2;
            float4 b4 = *(const float4*)&bias[(m0 + mm) * CZ + c0 + c4];
            bs[mm][c4 + 0] = b4.x; bs[mm][c4 + 1] = b4.y;
            bs[mm][c4 + 2] = b4.z; bs[mm][c4 + 3] = b4.w;
        }
        __syncthreads();
#pragma unroll
        for (int cc = 0; cc < 32; cc++) {
            float b = bs[tid][cc];
            const float4* wrow = (const float4*)&wzs[c0 + cc][0];
            float4 w0 = wrow[0], w1 = wrow[1], w2 = wrow[2], w3 = wrow[3];
            acc[0]  += b * w0.x; acc[1]  += b * w0.y; acc[2]  += b * w0.z; acc[3]  += b * w0.w;
            acc[4]  += b * w1.x; acc[5]  += b * w1.y; acc[6]  += b * w1.z; acc[7]  += b * w1.w;
            acc[8]  += b * w2.x; acc[9]  += b * w2.y; acc[10] += b * w2.z; acc[11] += b * w2.w;
            acc[12] += b * w3.x; acc[13] += b * w3.y; acc[14] += b * w3.z; acc[15] += b * w3.w;
        }
    }

    const int m = m0 + tid;
    const float madd = (1.f - mask[m & (CS - 1)]) * (-NEG_INF);
#pragma unroll
    for (int h = 0; h < HH; h++)
        g_z[h * (CS * CS) + m] = acc[h] + madd;
}

// ============================================================
// Flash attention with tf32 mma for QK^T and P@V.
// Block = (head h, 64-row i tile), j tile = 32, 256 threads = 8 warps.
// S tile 64x32: warp(4x2) -> 16x16 each (2 n-atoms).
// O tile 64x64: warp(4x2) -> 16x32 each (4 n-atoms).
// ============================================================
__global__ void __launch_bounds__(256) attn_kernel()
{
    __shared__ uint32_t Qs[64][68];    // tf32 [i][d], stride 68 (==4 mod 32)
    __shared__ uint32_t Ks[32][68];    // tf32 [j][d]
    __shared__ uint32_t Vs[32][72];    // tf32 [j][d], stride 72 (==8 mod 32)
    __shared__ float    Ss[64][36];    // logits / probs
    __shared__ float m_s[64], l_s[64], scale_s[64];

    const int tid  = threadIdx.x;
    const int w    = tid >> 5;
    const int lane = tid & 31;
    const int g    = lane >> 2;
    const int tq   = lane & 3;
    const int h    = blockIdx.y;
    const int i0   = blockIdx.x * 64;

    const int srow = (w & 3) * 16;     // S warp tile
    const int scol = (w >> 2) * 16;
    const int orow = (w & 3) * 16;     // O warp tile
    const int ocol = (w >> 2) * 32;

    // load Q tile [64][64] -> tf32
#pragma unroll
    for (int it = 0; it < 4; it++) {
        int slot = tid + it * 256;
        int row  = slot >> 4;
        int d4   = (slot & 15) << 2;
        float4 q4 = *(const float4*)&g_q[(i0 + row) * CS + h * DD + d4];
        Qs[row][d4 + 0] = f2tf(q4.x); Qs[row][d4 + 1] = f2tf(q4.y);
        Qs[row][d4 + 2] = f2tf(q4.z); Qs[row][d4 + 3] = f2tf(q4.w);
    }
    if (tid < 64) { m_s[tid] = -1e30f; l_s[tid] = 0.f; }

    float oacc[4][4];
#pragma unroll
    for (int na = 0; na < 4; na++)
#pragma unroll
        for (int r = 0; r < 4; r++) oacc[na][r] = 0.f;

    for (int j0 = 0; j0 < CS; j0 += 32) {
        // stage K, V tiles (32 x 64) -> tf32
#pragma unroll
        for (int it = 0; it < 2; it++) {
            int slot = tid + it * 256;
            int row  = slot >> 4;
            int d4   = (slot & 15) << 2;
            float4 k4 = *(const float4*)&g_k[(j0 + row) * CS + h * DD + d4];
            Ks[row][d4 + 0] = f2tf(k4.x); Ks[row][d4 + 1] = f2tf(k4.y);
            Ks[row][d4 + 2] = f2tf(k4.z); Ks[row][d4 + 3] = f2tf(k4.w);
            float4 v4 = *(const float4*)&g_v[(j0 + row) * CS + h * DD + d4];
            Vs[row][d4 + 0] = f2tf(v4.x); Vs[row][d4 + 1] = f2tf(v4.y);
            Vs[row][d4 + 2] = f2tf(v4.z); Vs[row][d4 + 3] = f2tf(v4.w);
        }
        __syncthreads();

        // ---- S = Q K^T via mma: warp computes 16x16 (2 n-atoms) ----
        float sc[2][4];
#pragma unroll
        for (int na = 0; na < 2; na++)
#pragma unroll
            for (int r = 0; r < 4; r++) sc[na][r] = 0.f;

#pragma unroll
        for (int kc = 0; kc < 8; kc++) {
            const int kb = kc * 8;
            uint32_t af[4];
            af[0] = Qs[srow + g][kb + tq];
            af[1] = Qs[srow + g + 8][kb + tq];
            af[2] = Qs[srow + g][kb + tq + 4];
            af[3] = Qs[srow + g + 8][kb + tq + 4];
            uint32_t bf[2][2];
#pragma unroll
            for (int na = 0; na < 2; na++) {
                const int jb = scol + na * 8 + g;
                bf[na][0] = Ks[jb][kb + tq];
                bf[na][1] = Ks[jb][kb + tq + 4];
            }
#pragma unroll
            for (int na = 0; na < 2; na++)
                mma_tf32(sc[na], af, bf[na]);
        }

        // write logits (qk/8 + z) to Ss
#pragma unroll
        for (int na = 0; na < 2; na++) {
            const int col  = scol + na * 8 + tq * 2;
            const int gi0  = i0 + srow + g;
            const long zb  = (long)h * (CS * CS);
            float2 z0 = *(const float2*)&g_z[zb + (long)gi0 * CS + j0 + col];
            float2 z1 = *(const float2*)&g_z[zb + (long)(gi0 + 8) * CS + j0 + col];
            Ss[srow + g][col]         = sc[na][0] * 0.125f + z0.x;
            Ss[srow + g][col + 1]     = sc[na][1] * 0.125f + z0.y;
            Ss[srow + g + 8][col]     = sc[na][2] * 0.125f + z1.x;
            Ss[srow + g + 8][col + 1] = sc[na][3] * 0.125f + z1.y;
        }
        __syncthreads();

        // ---- online softmax row stats: 4 threads per row ----
        {
            const int row = tid >> 2, seg = tid & 3;
            float mx = -1e30f;
#pragma unroll
            for (int jj = 0; jj < 8; jj++)
                mx = fmaxf(mx, Ss[row][(seg << 3) + jj]);
            mx = fmaxf(mx, __shfl_xor_sync(0xffffffffu, mx, 1));
            mx = fmaxf(mx, __shfl_xor_sync(0xffffffffu, mx, 2));
            const float m_old = m_s[row];
            const float m_new = fmaxf(m_old, mx);
            float sum = 0.f;
#pragma unroll
            for (int jj = 0; jj < 8; jj++) {
                float p = __expf(Ss[row][(seg << 3) + jj] - m_new);
                Ss[row][(seg << 3) + jj] = p;
                sum += p;
            }
            sum += __shfl_xor_sync(0xffffffffu, sum, 1);
            sum += __shfl_xor_sync(0xffffffffu, sum, 2);
            if (seg == 0) {
                float scl = __expf(m_old - m_new);
                l_s[row] = l_s[row] * scl + sum;
                m_s[row] = m_new;
                scale_s[row] = scl;
            }
        }
        __syncthreads();

        // ---- rescale O, accumulate P @ V via mma ----
        {
            const float s0 = scale_s[orow + g];
            const float s1 = scale_s[orow + g + 8];
#pragma unroll
            for (int na = 0; na < 4; na++) {
                oacc[na][0] *= s0; oacc[na][1] *= s0;
                oacc[na][2] *= s1; oacc[na][3] *= s1;
            }
        }
#pragma unroll
        for (int kc = 0; kc < 4; kc++) {
            const int kb = kc * 8;
            uint32_t af[4];
            af[0] = f2tf(Ss[orow + g][kb + tq]);
            af[1] = f2tf(Ss[orow + g + 8][kb + tq]);
            af[2] = f2tf(Ss[orow + g][kb + tq + 4]);
            af[3] = f2tf(Ss[orow + g + 8][kb + tq + 4]);
            uint32_t bf[4][2];
#pragma unroll
            for (int na = 0; na < 4; na++) {
                const int db = ocol + na * 8 + g;
                bf[na][0] = Vs[kb + tq][db];
                bf[na][1] = Vs[kb + tq + 4][db];
            }
#pragma unroll
            for (int na = 0; na < 4; na++)
                mma_tf32(oacc[na], af, bf[na]);
        }
        __syncthreads();
    }

    // finalize: divide by l, write o[i, h*64+d]
    {
        const float inv0 = 1.f / l_s[orow + g];
        const float inv1 = 1.f / l_s[orow + g + 8];
        const int r0 = i0 + orow + g;
#pragma unroll
        for (int na = 0; na < 4; na++) {
            const int col = h * DD + ocol + na * 8 + tq * 2;
            *(float2*)&g_o[r0 * CS + col] =
                make_float2(oacc[na][0] * inv0, oacc[na][1] * inv0);
            *(float2*)&g_o[(r0 + 8) * CS + col] =
                make_float2(oacc[na][2] * inv1, oacc[na][3] * inv1);
        }
    }
}

// ============================================================
// launch — kernel launches ONLY (graph-capturable)
// ============================================================
extern "C" void kernel_launch(void* const* d_in, const int* in_sizes, int n_in,
                              void* d_out, int out_size)
{
    const float* s    = (const float*)d_in[0];
    const float* k_in = (const float*)d_in[1];
    const float* mask = (const float*)d_in[2];
    const float* bias = (const float*)d_in[3];
    const float* Wq   = (const float*)d_in[4];
    const float* bq   = (const float*)d_in[5];
    const float* Wk   = (const float*)d_in[6];
    const float* Wv   = (const float*)d_in[7];
    const float* Wg   = (const float*)d_in[8];
    const float* Wo   = (const float*)d_in[9];
    const float* Wz   = (const float*)d_in[10];
    // d_in[11] = multiplicity (==1 for b=1) -> identity, ignored
    float* out = (float*)d_out;

    dim3 gg(CS / 64, CS / 128);   // 16 x 8 = 128 blocks

    gemm_q<<<gg, 256>>>(s, Wq, bq);
    gemm_k<<<gg, 256>>>(k_in, Wk);
    gemm_v<<<gg, 256>>>(k_in, Wv);
    gemm_g<<<gg, 256>>>(s, Wg);

    z_kernel<<<(CS * CS) / 256, 256>>>(bias, Wz, mask);

    attn_kernel<<<dim3(CS / 64, HH), 256>>>();

    gemm_out<<<gg, 256>>>(Wo, out);
}